// round 1
// baseline (speedup 1.0000x reference)
#include <cuda_runtime.h>
#include <cstdint>

// Problem constants (fixed by the dataset)
#define B_SZ   16
#define IN_F   8192
#define OUT_F  8192
#define GRP    128          // scale group size along in-features
#define NGRP   (IN_F / GRP) // 64
#define CHUNK  2048         // columns staged in smem per phase
#define NCHUNK (IN_F / CHUNK)
#define GPC    (CHUNK / GRP)   // 16 groups per chunk
#define XPAD   20              // floats per staged column (16 used, 80B stride -> conflict-free)
#define THREADS 256
#define WARPS   8
#define ROWS_PER_WARP 8
#define ROWS_PER_BLOCK (WARPS * ROWS_PER_WARP)  // 64
#define SMEM_BYTES (CHUNK * XPAD * 4)           // 163840

typedef unsigned long long ull;

__device__ __forceinline__ ull pack2(float v) {
    ull r;
    asm("mov.b64 %0, {%1, %1};" : "=l"(r) : "f"(v));
    return r;
}
__device__ __forceinline__ void fma2(ull& d, ull a, ull b) {
    asm("fma.rn.f32x2 %0, %1, %2, %0;" : "+l"(d) : "l"(a), "l"(b));
}
__device__ __forceinline__ ull add2(ull a, ull b) {
    ull r;
    asm("add.rn.f32x2 %0, %1, %2;" : "=l"(r) : "l"(a), "l"(b));
    return r;
}
__device__ __forceinline__ void unpack2(ull v, float& lo, float& hi) {
    asm("mov.b64 {%0, %1}, %2;" : "=f"(lo), "=f"(hi) : "l"(v));
}

__global__ void __launch_bounds__(THREADS, 1)
axcore_linear_kernel(const float* __restrict__ x,
                     const float* __restrict__ W,
                     const float* __restrict__ scale,
                     const float* __restrict__ bias,
                     float* __restrict__ out)
{
    extern __shared__ float smemX[]; // [CHUNK][XPAD]

    const int tid  = threadIdx.x;
    const int lane = tid & 31;
    const int warp = tid >> 5;
    const int row0 = blockIdx.x * ROWS_PER_BLOCK + warp * ROWS_PER_WARP;

    // acc[r][bp] : f32x2 over batch pair (2bp, 2bp+1), per output row r
    ull acc[ROWS_PER_WARP][8];
#pragma unroll
    for (int r = 0; r < ROWS_PER_WARP; r++)
#pragma unroll
        for (int bp = 0; bp < 8; bp++) acc[r][bp] = 0ull;

    float wA[ROWS_PER_WARP][4], wB[ROWS_PER_WARP][4];
    float sA[ROWS_PER_WARP], sB[ROWS_PER_WARP];

    for (int ci = 0; ci < NCHUNK; ci++) {
        const int cbase = ci * CHUNK;

        // ---- stage x chunk transposed into smem: smemX[j][b], 80B column stride
        for (int idx = tid; idx < CHUNK * B_SZ; idx += THREADS) {
            const int b = idx & 15;
            const int j = idx >> 4;
            smemX[j * XPAD + b] = x[b * IN_F + cbase + j];
        }
        __syncthreads();

        // ---- weight/scale prefetch for group 0 of this chunk
        {
            const float* wp = W + cbase + lane;
#pragma unroll
            for (int r = 0; r < ROWS_PER_WARP; r++) {
                const float* rowp = wp + (size_t)(row0 + r) * IN_F;
#pragma unroll
                for (int k = 0; k < 4; k++) wA[r][k] = __ldg(rowp + 32 * k);
                sA[r] = __ldg(scale + (size_t)(row0 + r) * NGRP + ci * GPC);
            }
        }

        // ---- 16 groups per chunk, ping-pong W buffers (unroll by 2)
        for (int g = 0; g < GPC; g += 2) {
            // prefetch g+1 -> B
            {
                const float* wp = W + cbase + (g + 1) * GRP + lane;
#pragma unroll
                for (int r = 0; r < ROWS_PER_WARP; r++) {
                    const float* rowp = wp + (size_t)(row0 + r) * IN_F;
#pragma unroll
                    for (int k = 0; k < 4; k++) wB[r][k] = __ldg(rowp + 32 * k);
                    sB[r] = __ldg(scale + (size_t)(row0 + r) * NGRP + ci * GPC + g + 1);
                }
            }
            // compute group g with A
#pragma unroll
            for (int k = 0; k < 4; k++) {
                const int j = g * GRP + lane + 32 * k; // chunk-local column
                const ulonglong2* px =
                    reinterpret_cast<const ulonglong2*>(smemX + j * XPAD);
                ull x2[8];
#pragma unroll
                for (int qb = 0; qb < 4; qb++) {
                    ulonglong2 v = px[qb];
                    x2[2 * qb] = v.x;
                    x2[2 * qb + 1] = v.y;
                }
#pragma unroll
                for (int r = 0; r < ROWS_PER_WARP; r++) {
                    const ull wp2 = pack2(wA[r][k] * sA[r]);
#pragma unroll
                    for (int bp = 0; bp < 8; bp++) fma2(acc[r][bp], wp2, x2[bp]);
                }
            }
            // prefetch g+2 -> A (if any)
            if (g + 2 < GPC) {
                const float* wp = W + cbase + (g + 2) * GRP + lane;
#pragma unroll
                for (int r = 0; r < ROWS_PER_WARP; r++) {
                    const float* rowp = wp + (size_t)(row0 + r) * IN_F;
#pragma unroll
                    for (int k = 0; k < 4; k++) wA[r][k] = __ldg(rowp + 32 * k);
                    sA[r] = __ldg(scale + (size_t)(row0 + r) * NGRP + ci * GPC + g + 2);
                }
            }
            // compute group g+1 with B
#pragma unroll
            for (int k = 0; k < 4; k++) {
                const int j = (g + 1) * GRP + lane + 32 * k;
                const ulonglong2* px =
                    reinterpret_cast<const ulonglong2*>(smemX + j * XPAD);
                ull x2[8];
#pragma unroll
                for (int qb = 0; qb < 4; qb++) {
                    ulonglong2 v = px[qb];
                    x2[2 * qb] = v.x;
                    x2[2 * qb + 1] = v.y;
                }
#pragma unroll
                for (int r = 0; r < ROWS_PER_WARP; r++) {
                    const ull wp2 = pack2(wB[r][k] * sB[r]);
#pragma unroll
                    for (int bp = 0; bp < 8; bp++) fma2(acc[r][bp], wp2, x2[bp]);
                }
            }
        }
        __syncthreads(); // compute done before next chunk overwrites smem
    }

    // ---- cross-lane reduction (butterfly; all lanes end with full sums)
#pragma unroll
    for (int r = 0; r < ROWS_PER_WARP; r++)
#pragma unroll
        for (int bp = 0; bp < 8; bp++) {
            ull v = acc[r][bp];
#pragma unroll
            for (int off = 16; off > 0; off >>= 1) {
                ull o = __shfl_xor_sync(0xffffffffu, v, off);
                v = add2(v, o);
            }
            acc[r][bp] = v;
        }

    // ---- writeback: lane (r*4 + bp/2) stores batch pairs of (row0+r, bp)
#pragma unroll
    for (int r = 0; r < ROWS_PER_WARP; r++) {
#pragma unroll
        for (int bp = 0; bp < 8; bp++) {
            if (lane == r * 4 + (bp >> 1)) {
                const int row = row0 + r;
                const float bv = __ldg(bias + row);
                float lo, hi;
                unpack2(acc[r][bp], lo, hi);
                out[(size_t)(2 * bp) * OUT_F + row] = lo + bv;
                out[(size_t)(2 * bp + 1) * OUT_F + row] = hi + bv;
            }
        }
    }
}

extern "C" void kernel_launch(void* const* d_in, const int* in_sizes, int n_in,
                              void* d_out, int out_size)
{
    const float* x     = (const float*)d_in[0]; // [16, 8192]
    const float* W     = (const float*)d_in[1]; // [8192, 8192]
    const float* scale = (const float*)d_in[2]; // [8192, 64]
    const float* bias  = (const float*)d_in[3]; // [1, 8192]
    // d_in[4] = types — constant lookup in reference, no float math: unused
    float* out = (float*)d_out;                 // [16, 8192]

    cudaFuncSetAttribute(axcore_linear_kernel,
                         cudaFuncAttributeMaxDynamicSharedMemorySize, SMEM_BYTES);

    dim3 grid(OUT_F / ROWS_PER_BLOCK); // 128
    dim3 block(THREADS);               // 256
    axcore_linear_kernel<<<grid, block, SMEM_BYTES>>>(x, W, scale, bias, out);
}